// round 2
// baseline (speedup 1.0000x reference)
#include <cuda_runtime.h>
#include <math.h>

// Problem constants (fixed by setup_inputs)
#define BB 4
#define SS 8192
#define DD 512
#define HH 8
#define HD 64
#define BH 32      // B*H
#define UU 45      // int(5*ln(8193)) = 45 selected queries per (b,h)
#define NSPLIT 16
#define CHUNK 512  // SS / NSPLIT

// ------------------------- device scratch -------------------------
static __device__ __align__(16) float g_k[(size_t)BH*SS*HD];      // 64 MB, [bh][s][d]
static __device__ __align__(16) float g_v[(size_t)BH*SS*HD];      // 64 MB, [bh][s][d]
static __device__ float g_sp[BH*SS];                               // sparsity ||q||^2
static __device__ int   g_top[BH*UU];
static __device__ __align__(16) float g_selq[BH*UU*HD];
static __device__ float g_selctx[BH*UU*HD];
static __device__ float g_vsum[BH*HD];
static __device__ __align__(16) float g_base[BB*DD];
static __device__ float g_pm[BH*NSPLIT*UU];
static __device__ float g_pl[BH*NSPLIT*UU];
static __device__ __align__(16) float g_pacc[(size_t)BH*NSPLIT*UU*HD];

// ------------------------- fused projection GEMM -------------------------
// C = X @ W + bias, tile 128x128x16, 256 threads, 8x8 microtile.
// MODE 0: reduce each row's per-head sum of squares into g_sp (q path)
// MODE 1: write head-major k   MODE 2: write head-major v
template<int MODE>
__global__ __launch_bounds__(256)
void proj_gemm(const float* __restrict__ X, const float* __restrict__ W,
               const float* __restrict__ bias)
{
    __shared__ __align__(16) float As[16][132];   // transposed: As[k][m]
    __shared__ __align__(16) float Bs[16][128];
    const int m0 = blockIdx.x * 128;
    const int n0 = blockIdx.y * 128;
    const int tid = threadIdx.x;
    const int tx = tid & 15;
    const int ty = tid >> 4;

    float acc[8][8];
#pragma unroll
    for (int i = 0; i < 8; i++)
#pragma unroll
        for (int j = 0; j < 8; j++) acc[i][j] = 0.f;

    for (int k0 = 0; k0 < DD; k0 += 16) {
#pragma unroll
        for (int p = 0; p < 2; p++) {
            int id = tid + p * 256;
            int r = id >> 2;
            int kv = (id & 3) * 4;
            float4 v = *(const float4*)(X + (size_t)(m0 + r) * DD + k0 + kv);
            As[kv + 0][r] = v.x;
            As[kv + 1][r] = v.y;
            As[kv + 2][r] = v.z;
            As[kv + 3][r] = v.w;
        }
#pragma unroll
        for (int p = 0; p < 2; p++) {
            int id = tid + p * 256;
            int r = id >> 5;
            int c = (id & 31) * 4;
            *(float4*)(&Bs[r][c]) = *(const float4*)(W + (size_t)(k0 + r) * DD + n0 + c);
        }
        __syncthreads();
#pragma unroll
        for (int kk = 0; kk < 16; kk++) {
            float a[8], b[8];
            *(float4*)(a)     = *(const float4*)(&As[kk][ty * 8]);
            *(float4*)(a + 4) = *(const float4*)(&As[kk][ty * 8 + 4]);
            *(float4*)(b)     = *(const float4*)(&Bs[kk][tx * 8]);
            *(float4*)(b + 4) = *(const float4*)(&Bs[kk][tx * 8 + 4]);
#pragma unroll
            for (int i = 0; i < 8; i++)
#pragma unroll
                for (int j = 0; j < 8; j++)
                    acc[i][j] = fmaf(a[i], b[j], acc[i][j]);
        }
        __syncthreads();
    }

    float bv[8];
#pragma unroll
    for (int j = 0; j < 8; j++) bv[j] = bias[n0 + tx * 8 + j];

    const int h = blockIdx.y * 2 + (tx >> 3);   // two heads per 128-wide tile

    if (MODE == 0) {
#pragma unroll
        for (int i = 0; i < 8; i++) {
            float ss = 0.f;
#pragma unroll
            for (int j = 0; j < 8; j++) {
                float c = acc[i][j] + bv[j];
                ss = fmaf(c, c, ss);
            }
            // reduce across the 8 tx lanes of the same head (within warp)
            ss += __shfl_xor_sync(0xffffffffu, ss, 1);
            ss += __shfl_xor_sync(0xffffffffu, ss, 2);
            ss += __shfl_xor_sync(0xffffffffu, ss, 4);
            if ((tx & 7) == 0) {
                int m = m0 + ty * 8 + i;
                int b = m >> 13;          // /SS
                int s = m & (SS - 1);
                g_sp[((size_t)(b * HH + h)) * SS + s] = ss;
            }
        }
    } else {
        float* __restrict__ dst = (MODE == 1) ? g_k : g_v;
        int d0 = (tx & 7) * 8;
#pragma unroll
        for (int i = 0; i < 8; i++) {
            int m = m0 + ty * 8 + i;
            int b = m >> 13;
            int s = m & (SS - 1);
            float* o = dst + (((size_t)(b * HH + h)) * SS + s) * HD + d0;
            float4 o1, o2;
            o1.x = acc[i][0] + bv[0]; o1.y = acc[i][1] + bv[1];
            o1.z = acc[i][2] + bv[2]; o1.w = acc[i][3] + bv[3];
            o2.x = acc[i][4] + bv[4]; o2.y = acc[i][5] + bv[5];
            o2.z = acc[i][6] + bv[6]; o2.w = acc[i][7] + bv[7];
            *(float4*)(o)     = o1;
            *(float4*)(o + 4) = o2;
        }
    }
}

// ------------------------- top-k (iterative selection) -------------------------
__global__ __launch_bounds__(256) void topk_kernel()
{
    __shared__ float sv[SS];    // 32 KB
    __shared__ float rv[256];
    __shared__ int   ri[256];
    const int bh = blockIdx.x;
    const int tid = threadIdx.x;
    for (int j = tid; j < SS; j += 256) sv[j] = g_sp[(size_t)bh * SS + j];
    __syncthreads();
    for (int it = 0; it < UU; it++) {
        float best = -INFINITY; int bi = SS;
        for (int j = tid; j < SS; j += 256) {
            float v = sv[j];
            if (v > best) { best = v; bi = j; }     // keeps lowest index on ties
        }
        rv[tid] = best; ri[tid] = bi;
        __syncthreads();
        for (int off = 128; off > 0; off >>= 1) {
            if (tid < off) {
                float v2 = rv[tid + off]; int i2 = ri[tid + off];
                if (v2 > rv[tid] || (v2 == rv[tid] && i2 < ri[tid])) {
                    rv[tid] = v2; ri[tid] = i2;
                }
            }
            __syncthreads();
        }
        if (tid == 0) { g_top[bh * UU + it] = ri[0]; sv[ri[0]] = -INFINITY; }
        __syncthreads();
    }
}

// ------------------------- recompute selected q rows -------------------------
__global__ __launch_bounds__(64)
void selq_kernel(const float* __restrict__ X, const float* __restrict__ Wq,
                 const float* __restrict__ bq)
{
    const int bh = blockIdx.x, u = blockIdx.y;
    const int b = bh >> 3, h = bh & 7;
    const int d = threadIdx.x;
    const int s = g_top[bh * UU + u];
    const float* xr = X + ((size_t)b * SS + s) * DD;
    const float* wc = Wq + h * HD + d;
    float a = bq[h * HD + d];
    for (int kk = 0; kk < DD; kk++)
        a = fmaf(xr[kk], wc[(size_t)kk * DD], a);
    g_selq[(bh * UU + u) * HD + d] = a;
}

// ------------------------- v mean -------------------------
__global__ void zero_vsum()
{
    int i = blockIdx.x * 256 + threadIdx.x;
    if (i < BH * HD) g_vsum[i] = 0.f;
}

__global__ __launch_bounds__(256) void vsum_kernel()
{
    const int bh = blockIdx.x, ch = blockIdx.y;   // 32 chunks of 256 rows
    const int d = threadIdx.x & 63;
    const int r0 = threadIdx.x >> 6;
    const float* vp = g_v + ((size_t)bh * SS + ch * 256) * HD;
    float s = 0.f;
    for (int s_ = r0; s_ < 256; s_ += 4)
        s += vp[s_ * HD + d];
    atomicAdd(&g_vsum[bh * HD + d], s);
}

// ------------------------- attention (flash split-K over S) -------------------------
__global__ __launch_bounds__(256)
void attn_kernel()
{
    __shared__ __align__(16) float sq[UU][64];    // pre-scaled queries
    __shared__ float KV[64][65];                  // K then V tile (reused)
    __shared__ __align__(16) float P[UU][68];     // scores / probabilities
    __shared__ float sm[UU], sl[UU], salpha[UU];

    const int bh = blockIdx.x;
    const int sp = blockIdx.y;
    const int tid = threadIdx.x;
    const int lane = tid & 63;    // j (keys) or d (values)
    const int qg = tid >> 6;      // 0..3

    for (int i = tid; i < UU * 64; i += 256)
        sq[i >> 6][i & 63] = g_selq[(size_t)bh * UU * 64 + i] * 0.125f;  // hd^-0.5
    if (tid < UU) { sm[tid] = -INFINITY; sl[tid] = 0.f; }

    float acc[12];
#pragma unroll
    for (int qi = 0; qi < 12; qi++) acc[qi] = 0.f;

    const float* kbase = g_k + ((size_t)bh * SS + sp * CHUNK) * HD;
    const float* vbase = g_v + ((size_t)bh * SS + sp * CHUNK) * HD;
    __syncthreads();

    for (int t = 0; t < CHUNK / 64; t++) {
        // load K tile [64][64]
        const float* kp = kbase + t * 64 * HD;
#pragma unroll
        for (int p = 0; p < 4; p++) {
            int id = tid + p * 256;
            int r = id >> 4;
            int c = (id & 15) * 4;
            float4 v = *(const float4*)(kp + r * HD + c);
            KV[r][c + 0] = v.x; KV[r][c + 1] = v.y;
            KV[r][c + 2] = v.z; KV[r][c + 3] = v.w;
        }
        __syncthreads();

        // QK^T: thread (j=lane, qg) -> scores for q = qg + 4*qi
        float dots[12];
#pragma unroll
        for (int qi = 0; qi < 12; qi++) dots[qi] = 0.f;
#pragma unroll
        for (int d4 = 0; d4 < 64; d4 += 4) {
            float k0 = KV[lane][d4 + 0];
            float k1 = KV[lane][d4 + 1];
            float k2 = KV[lane][d4 + 2];
            float k3 = KV[lane][d4 + 3];
#pragma unroll
            for (int qi = 0; qi < 12; qi++) {
                int q = qg + qi * 4;
                if (q < UU) {
                    float4 qv = *(const float4*)(&sq[q][d4]);
                    dots[qi] += qv.x * k0 + qv.y * k1 + qv.z * k2 + qv.w * k3;
                }
            }
        }
#pragma unroll
        for (int qi = 0; qi < 12; qi++) {
            int q = qg + qi * 4;
            if (q < UU) P[q][lane] = dots[qi];
        }
        __syncthreads();

        // running max update (45 threads)
        if (tid < UU) {
            float mloc = -INFINITY;
#pragma unroll
            for (int j = 0; j < 64; j++) mloc = fmaxf(mloc, P[tid][j]);
            float mnew = fmaxf(sm[tid], mloc);
            salpha[tid] = __expf(sm[tid] - mnew);    // exp(-inf)=0 on first tile
            sm[tid] = mnew;
        }
        // load V tile into same buffer (QK reads of KV completed at last sync)
        const float* vp = vbase + t * 64 * HD;
#pragma unroll
        for (int p = 0; p < 4; p++) {
            int id = tid + p * 256;
            int r = id >> 4;
            int c = (id & 15) * 4;
            float4 v = *(const float4*)(vp + r * HD + c);
            KV[r][c + 0] = v.x; KV[r][c + 1] = v.y;
            KV[r][c + 2] = v.z; KV[r][c + 3] = v.w;
        }
        __syncthreads();

        // exponentiate + rescale accumulators
#pragma unroll
        for (int qi = 0; qi < 12; qi++) {
            int q = qg + qi * 4;
            if (q < UU) {
                P[q][lane] = __expf(P[q][lane] - sm[q]);
                acc[qi] *= salpha[q];
            }
        }
        __syncthreads();

        // l accumulation (45 threads)
        if (tid < UU) {
            float lsum = 0.f;
#pragma unroll
            for (int j = 0; j < 64; j++) lsum += P[tid][j];
            sl[tid] = sl[tid] * salpha[tid] + lsum;
        }
        // P @ V: thread (d=lane, qg)
#pragma unroll
        for (int j4 = 0; j4 < 64; j4 += 4) {
            float v0 = KV[j4 + 0][lane];
            float v1 = KV[j4 + 1][lane];
            float v2 = KV[j4 + 2][lane];
            float v3 = KV[j4 + 3][lane];
#pragma unroll
            for (int qi = 0; qi < 12; qi++) {
                int q = qg + qi * 4;
                if (q < UU) {
                    float4 pv = *(const float4*)(&P[q][j4]);
                    acc[qi] += pv.x * v0 + pv.y * v1 + pv.z * v2 + pv.w * v3;
                }
            }
        }
        __syncthreads();
    }

    const int pbase = (bh * NSPLIT + sp) * UU;
    if (tid < UU) { g_pm[pbase + tid] = sm[tid]; g_pl[pbase + tid] = sl[tid]; }
#pragma unroll
    for (int qi = 0; qi < 12; qi++) {
        int q = qg + qi * 4;
        if (q < UU) g_pacc[((size_t)(pbase + q)) * HD + lane] = acc[qi];
    }
}

// ------------------------- split-K merge -------------------------
__global__ __launch_bounds__(64) void merge_kernel()
{
    const int bh = blockIdx.x, u = blockIdx.y;
    const int d = threadIdx.x;
    float M = -INFINITY;
#pragma unroll
    for (int i = 0; i < NSPLIT; i++)
        M = fmaxf(M, g_pm[(bh * NSPLIT + i) * UU + u]);
    float L = 0.f, ctx = 0.f;
    for (int i = 0; i < NSPLIT; i++) {
        int pi = (bh * NSPLIT + i) * UU + u;
        float w = __expf(g_pm[pi] - M);
        L += g_pl[pi] * w;
        ctx += g_pacc[(size_t)pi * HD + d] * w;
    }
    g_selctx[(bh * UU + u) * HD + d] = ctx / L;
}

// ------------------------- output base, broadcast, corrections -------------------------
__global__ __launch_bounds__(512)
void base_kernel(const float* __restrict__ Wo, const float* __restrict__ bo)
{
    __shared__ float vm[DD];
    const int b = blockIdx.x;
    const int n = threadIdx.x;
    vm[n] = g_vsum[b * DD + n] * (1.f / SS);
    __syncthreads();
    float a = bo[n];
    for (int kk = 0; kk < DD; kk++)
        a = fmaf(vm[kk], Wo[(size_t)kk * DD + n], a);
    g_base[b * DD + n] = a;
}

__global__ __launch_bounds__(256) void bcast_kernel(float* __restrict__ out)
{
    __shared__ float4 bs[128];
    const int row0 = blockIdx.x * 16;     // 16 rows per block, never crosses batch
    const int b = row0 >> 13;
    if (threadIdx.x < 128)
        bs[threadIdx.x] = ((const float4*)(g_base + b * DD))[threadIdx.x];
    __syncthreads();
    float4* o = (float4*)out + (size_t)row0 * 128;
    for (int i = threadIdx.x; i < 16 * 128; i += 256)
        o[i] = bs[i & 127];
}

__global__ __launch_bounds__(512)
void corr_kernel(const float* __restrict__ Wo, float* __restrict__ out)
{
    __shared__ float delta[64];
    __shared__ int ssel;
    const int bh = blockIdx.x, u = blockIdx.y;
    const int b = bh >> 3, h = bh & 7;
    const int tid = threadIdx.x;
    if (tid == 0) ssel = g_top[bh * UU + u];
    if (tid < 64)
        delta[tid] = g_selctx[(bh * UU + u) * HD + tid]
                   - g_vsum[bh * HD + tid] * (1.f / SS);
    __syncthreads();
    const int s = ssel;
    float a = 0.f;
#pragma unroll
    for (int d = 0; d < 64; d++)
        a = fmaf(delta[d], Wo[(size_t)(h * HD + d) * DD + tid], a);
    // multiple heads may select the same s -> additive
    atomicAdd(out + ((size_t)b * SS + s) * DD + tid, a);
}

// ------------------------- launch -------------------------
extern "C" void kernel_launch(void* const* d_in, const int* in_sizes, int n_in,
                              void* d_out, int out_size)
{
    (void)in_sizes; (void)n_in; (void)out_size;
    const float* x  = (const float*)d_in[0];
    const float* Wq = (const float*)d_in[1];
    const float* bq = (const float*)d_in[2];
    const float* Wk = (const float*)d_in[3];
    const float* bk = (const float*)d_in[4];
    const float* Wv = (const float*)d_in[5];
    const float* bv = (const float*)d_in[6];
    const float* Wo = (const float*)d_in[7];
    const float* bo = (const float*)d_in[8];
    float* out = (float*)d_out;

    dim3 pg(BB * SS / 128, DD / 128);
    proj_gemm<0><<<pg, 256>>>(x, Wq, bq);     // sparsity only (no q store)
    proj_gemm<1><<<pg, 256>>>(x, Wk, bk);     // k head-major
    proj_gemm<2><<<pg, 256>>>(x, Wv, bv);     // v head-major
    topk_kernel<<<BH, 256>>>();
    selq_kernel<<<dim3(BH, UU), 64>>>(x, Wq, bq);
    zero_vsum<<<(BH * HD + 255) / 256, 256>>>();
    vsum_kernel<<<dim3(BH, 32), 256>>>();
    attn_kernel<<<dim3(BH, NSPLIT), 256>>>();
    merge_kernel<<<dim3(BH, UU), HD>>>();
    base_kernel<<<BB, DD>>>(Wo, bo);
    bcast_kernel<<<BB * SS / 16, 256>>>(out);
    corr_kernel<<<dim3(BH, UU), DD>>>(Wo, out);
}

// round 3
// speedup vs baseline: 1.0191x; 1.0191x over previous
#include <cuda_runtime.h>
#include <math.h>
#include <stdint.h>

// Problem constants (fixed by setup_inputs)
#define BB 4
#define SS 8192
#define DD 512
#define HH 8
#define HD 64
#define BH 32      // B*H
#define UU 45      // int(5*ln(8193)) = 45 selected queries per (b,h)
#define NC 64      // candidate count for exact refinement
#define NSPLIT 16
#define CHUNK 512  // SS / NSPLIT

// ------------------------- device scratch -------------------------
static __device__ __align__(16) float g_k[(size_t)BH*SS*HD];      // 64 MB [bh][s][d]
static __device__ __align__(16) float g_v[(size_t)BH*SS*HD];      // 64 MB [bh][s][d]
static __device__ float g_sp[BH*SS];                               // approx ||q||^2 (tf32)
static __device__ int   g_cand[BH*NC];
static __device__ float g_csp[BH*NC];                              // exact ||q||^2 of candidates
static __device__ __align__(16) float g_cq[BH*NC*HD];              // exact q rows of candidates
static __device__ int   g_top[BH*UU];
static __device__ __align__(16) float g_selq[BH*UU*HD];
static __device__ float g_selctx[BH*UU*HD];
static __device__ float g_vsum[BH*HD];
static __device__ __align__(16) float g_base[BB*DD];
static __device__ float g_pm[BH*NSPLIT*UU];
static __device__ float g_pl[BH*NSPLIT*UU];
static __device__ __align__(16) float g_pacc[(size_t)BH*NSPLIT*UU*HD];

__device__ __forceinline__ uint32_t f2tf(float f) {
    uint32_t u;
    asm("cvt.rna.tf32.f32 %0, %1;" : "=r"(u) : "f"(f));
    return u;
}

// ------------------------- zero kernels -------------------------
__global__ void zero_sp()
{
    int i = blockIdx.x * 256 + threadIdx.x;
    g_sp[i] = 0.f;                      // grid sized exactly BH*SS/256
    if (i < BH * HD) g_vsum[i] = 0.f;
}

// ------------------------- tensor-core projection GEMM (tf32) -------------------------
// C = X @ W + bias. Tile 128x128, k-chunk 32, 8 warps (2M x 4N), warp tile 64x32.
// mma.sync.m16n8k8.tf32, fragments pre-permuted in smem.
// MODE 0: q path -> accumulate per-head row sum of squares into g_sp (atomicAdd)
// MODE 1: write head-major k   MODE 2: write head-major v
template<int MODE>
__global__ __launch_bounds__(256)
void proj_tc(const float* __restrict__ X, const float* __restrict__ W,
             const float* __restrict__ bias)
{
    // A: 8 mblk x 4 kblk blocks, each 32 lanes x 4 regs (fragment order)
    __shared__ uint32_t sA[8 * 4 * 32 * 4];   // 4096 u32 = 16KB
    // B: 16 nblk x 4 kblk blocks, each 32 lanes x 2 regs
    __shared__ uint32_t sB[16 * 4 * 32 * 2];  // 4096 u32 = 16KB

    const int tid = threadIdx.x;
    const int m0 = blockIdx.x * 128;
    const int n0 = blockIdx.y * 128;

    const int ar = tid >> 3;         // 0..31 (A row within 32-row group)
    const int ac = tid & 7;          // 0..7  (x4 k cols)
    const int br = tid >> 5;         // 0..7  (B k row within 8-row group)
    const int bc = (tid & 31) * 4;   // B n col

    float4 pa[4], pb[4];

    // prefetch chunk 0
#pragma unroll
    for (int p = 0; p < 4; p++)
        pa[p] = *(const float4*)(X + (size_t)(m0 + ar + p * 32) * DD + ac * 4);
#pragma unroll
    for (int p = 0; p < 4; p++)
        pb[p] = *(const float4*)(W + (size_t)(br + p * 8) * DD + n0 + bc);

    float acc[4][4][4];
#pragma unroll
    for (int mi = 0; mi < 4; mi++)
#pragma unroll
        for (int ni = 0; ni < 4; ni++)
#pragma unroll
            for (int c = 0; c < 4; c++) acc[mi][ni][c] = 0.f;

    const int wid = tid >> 5, lane = tid & 31;
    const int mwarp = wid >> 2, nwarp = wid & 3;

    for (int ch = 0; ch < 16; ch++) {
        // stage prefetched regs into fragment-order smem (with tf32 rounding)
#pragma unroll
        for (int p = 0; p < 4; p++) {
            int r = ar + p * 32;
            int mblk = r >> 4, mrow = r & 15;
            float v[4] = {pa[p].x, pa[p].y, pa[p].z, pa[p].w};
#pragma unroll
            for (int j = 0; j < 4; j++) {
                int k = ac * 4 + j;
                int kblk = k >> 3, kcol = k & 7;
                int ln = (mrow & 7) * 4 + (kcol & 3);
                int slot = ((mrow >> 3) & 1) | (((kcol >> 2) & 1) << 1);
                sA[((mblk * 4 + kblk) * 32 + ln) * 4 + slot] = f2tf(v[j]);
            }
        }
#pragma unroll
        for (int p = 0; p < 4; p++) {
            int r = br + p * 8;
            int kblk = r >> 3, tg = r & 3, slot = (r >> 2) & 1;
            float v[4] = {pb[p].x, pb[p].y, pb[p].z, pb[p].w};
#pragma unroll
            for (int j = 0; j < 4; j++) {
                int n = bc + j;
                int nblk = n >> 3, col = n & 7;
                int ln = col * 4 + tg;
                sB[((nblk * 4 + kblk) * 32 + ln) * 2 + slot] = f2tf(v[j]);
            }
        }
        __syncthreads();

        // prefetch next chunk (in flight during compute)
        if (ch < 15) {
            int k0 = (ch + 1) * 32;
#pragma unroll
            for (int p = 0; p < 4; p++)
                pa[p] = *(const float4*)(X + (size_t)(m0 + ar + p * 32) * DD + k0 + ac * 4);
#pragma unroll
            for (int p = 0; p < 4; p++)
                pb[p] = *(const float4*)(W + (size_t)(k0 + br + p * 8) * DD + n0 + bc);
        }

#pragma unroll
        for (int kblk = 0; kblk < 4; kblk++) {
            uint32_t af[4][4];
            uint32_t bf[4][2];
#pragma unroll
            for (int mi = 0; mi < 4; mi++) {
                uint4 t = *(const uint4*)&sA[(((mwarp * 4 + mi) * 4 + kblk) * 32 + lane) * 4];
                af[mi][0] = t.x; af[mi][1] = t.y; af[mi][2] = t.z; af[mi][3] = t.w;
            }
#pragma unroll
            for (int ni = 0; ni < 4; ni++) {
                uint2 t = *(const uint2*)&sB[(((nwarp * 4 + ni) * 4 + kblk) * 32 + lane) * 2];
                bf[ni][0] = t.x; bf[ni][1] = t.y;
            }
#pragma unroll
            for (int mi = 0; mi < 4; mi++)
#pragma unroll
                for (int ni = 0; ni < 4; ni++) {
                    asm volatile(
                        "mma.sync.aligned.m16n8k8.row.col.f32.tf32.tf32.f32 "
                        "{%0,%1,%2,%3}, {%4,%5,%6,%7}, {%8,%9}, {%0,%1,%2,%3};\n"
                        : "+f"(acc[mi][ni][0]), "+f"(acc[mi][ni][1]),
                          "+f"(acc[mi][ni][2]), "+f"(acc[mi][ni][3])
                        : "r"(af[mi][0]), "r"(af[mi][1]), "r"(af[mi][2]), "r"(af[mi][3]),
                          "r"(bf[ni][0]), "r"(bf[ni][1]));
                }
        }
        __syncthreads();
    }

    // ---------------- epilogue ----------------
    const int g = lane >> 2, tg = lane & 3;

    // bias values for this thread's 8 columns
    float bn[4][2];
#pragma unroll
    for (int ni = 0; ni < 4; ni++) {
        int n = n0 + nwarp * 32 + ni * 8 + tg * 2;
        bn[ni][0] = bias[n];
        bn[ni][1] = bias[n + 1];
    }

    if (MODE == 0) {
        const int h = (n0 + nwarp * 32) >> 6;   // warp's 32 cols lie in one head
#pragma unroll
        for (int mi = 0; mi < 4; mi++) {
            int m = m0 + mwarp * 64 + mi * 16 + g;
            int b = m >> 13;
            float ss0 = 0.f, ss1 = 0.f;
#pragma unroll
            for (int ni = 0; ni < 4; ni++) {
                float c0 = acc[mi][ni][0] + bn[ni][0];
                float c1 = acc[mi][ni][1] + bn[ni][1];
                float c2 = acc[mi][ni][2] + bn[ni][0];
                float c3 = acc[mi][ni][3] + bn[ni][1];
                ss0 = fmaf(c0, c0, fmaf(c1, c1, ss0));
                ss1 = fmaf(c2, c2, fmaf(c3, c3, ss1));
            }
            ss0 += __shfl_xor_sync(0xffffffffu, ss0, 1);
            ss0 += __shfl_xor_sync(0xffffffffu, ss0, 2);
            ss1 += __shfl_xor_sync(0xffffffffu, ss1, 1);
            ss1 += __shfl_xor_sync(0xffffffffu, ss1, 2);
            if (tg == 0) {
                int s = m & (SS - 1);
                atomicAdd(&g_sp[(b * HH + h) * SS + s], ss0);
                atomicAdd(&g_sp[(b * HH + h) * SS + (s + 8)], ss1);
            }
        }
    } else {
        float* __restrict__ dst = (MODE == 1) ? g_k : g_v;
#pragma unroll
        for (int mi = 0; mi < 4; mi++) {
            int m = m0 + mwarp * 64 + mi * 16 + g;
            int b = m >> 13;
            int s = m & (SS - 1);
#pragma unroll
            for (int ni = 0; ni < 4; ni++) {
                int n = n0 + nwarp * 32 + ni * 8 + tg * 2;
                int h = n >> 6, d = n & 63;
                float2 lo = {acc[mi][ni][0] + bn[ni][0], acc[mi][ni][1] + bn[ni][1]};
                float2 hi = {acc[mi][ni][2] + bn[ni][0], acc[mi][ni][3] + bn[ni][1]};
                *(float2*)(dst + (((size_t)(b * HH + h)) * SS + s) * HD + d)       = lo;
                *(float2*)(dst + (((size_t)(b * HH + h)) * SS + s + 8) * HD + d)   = hi;
            }
        }
    }
}

// ------------------------- top-64 candidates (iterative, warp argmax) -------------------------
__global__ __launch_bounds__(256) void topk_kernel()
{
    __shared__ float sv[SS];    // 32 KB
    __shared__ float wv[8];
    __shared__ int   wi[8];
    const int bh = blockIdx.x;
    const int tid = threadIdx.x;
    const int lane = tid & 31, wid = tid >> 5;
    for (int j = tid; j < SS; j += 256) sv[j] = g_sp[bh * SS + j];
    __syncthreads();
    for (int it = 0; it < NC; it++) {
        float best = -INFINITY; int bi = 0;
        for (int j = tid; j < SS; j += 256) {
            float v = sv[j];
            if (v > best) { best = v; bi = j; }
        }
#pragma unroll
        for (int off = 16; off > 0; off >>= 1) {
            float ov = __shfl_down_sync(0xffffffffu, best, off);
            int   oi = __shfl_down_sync(0xffffffffu, bi, off);
            if (ov > best || (ov == best && oi < bi)) { best = ov; bi = oi; }
        }
        if (lane == 0) { wv[wid] = best; wi[wid] = bi; }
        __syncthreads();
        if (tid == 0) {
            float b = wv[0]; int x = wi[0];
#pragma unroll
            for (int w = 1; w < 8; w++)
                if (wv[w] > b || (wv[w] == b && wi[w] < x)) { b = wv[w]; x = wi[w]; }
            g_cand[bh * NC + it] = x;
            sv[x] = -INFINITY;
        }
        __syncthreads();
    }
}

// ------------------------- exact fp32 recompute of candidate q rows -------------------------
__global__ __launch_bounds__(64)
void cand_refine(const float* __restrict__ X, const float* __restrict__ Wq,
                 const float* __restrict__ bq)
{
    __shared__ float red[64];
    const int bh = blockIdx.x, u = blockIdx.y;
    const int b = bh >> 3, h = bh & 7;
    const int d = threadIdx.x;
    const int s = g_cand[bh * NC + u];
    const float* xr = X + ((size_t)b * SS + s) * DD;
    const float* wc = Wq + h * HD + d;
    float a = bq[h * HD + d];
    for (int kk = 0; kk < DD; kk++)
        a = fmaf(xr[kk], wc[(size_t)kk * DD], a);
    g_cq[(bh * NC + u) * HD + d] = a;
    red[d] = a * a;
    __syncthreads();
#pragma unroll
    for (int off = 32; off > 0; off >>= 1) {
        if (d < off) red[d] += red[d + off];
        __syncthreads();
    }
    if (d == 0) g_csp[bh * NC + u] = red[0];
}

// ------------------------- exact top-45 among candidates -------------------------
__global__ __launch_bounds__(64) void final_sel()
{
    __shared__ float vv[NC];
    __shared__ int   ssd[NC];
    __shared__ int   slot[UU];
    const int bh = blockIdx.x;
    const int tid = threadIdx.x;
    float myv = g_csp[bh * NC + tid];
    int   mys = g_cand[bh * NC + tid];
    vv[tid] = myv; ssd[tid] = mys;
    __syncthreads();
    int rank = 0;
#pragma unroll
    for (int j = 0; j < NC; j++) {
        float o = vv[j];
        if (o > myv || (o == myv && ssd[j] < mys)) rank++;
    }
    if (rank < UU) { g_top[bh * UU + rank] = mys; slot[rank] = tid; }
    __syncthreads();
    for (int u = 0; u < UU; u++) {
        int c = slot[u];
        g_selq[(bh * UU + u) * HD + tid] = g_cq[(bh * NC + c) * HD + tid];
    }
}

// ------------------------- v mean -------------------------
__global__ __launch_bounds__(256) void vsum_kernel()
{
    const int bh = blockIdx.x, ch = blockIdx.y;   // 32 chunks of 256 rows
    const int d = threadIdx.x & 63;
    const int r0 = threadIdx.x >> 6;
    const float* vp = g_v + ((size_t)bh * SS + ch * 256) * HD;
    float s = 0.f;
    for (int s_ = r0; s_ < 256; s_ += 4)
        s += vp[s_ * HD + d];
    atomicAdd(&g_vsum[bh * HD + d], s);
}

// ------------------------- attention (flash split-K over S) -------------------------
__global__ __launch_bounds__(256)
void attn_kernel()
{
    __shared__ __align__(16) float sq[UU][64];    // pre-scaled queries
    __shared__ float KV[64][65];                  // K then V tile (reused)
    __shared__ __align__(16) float P[UU][68];     // scores / probabilities
    __shared__ float sm[UU], sl[UU], salpha[UU];

    const int bh = blockIdx.x;
    const int sp = blockIdx.y;
    const int tid = threadIdx.x;
    const int lane = tid & 63;    // j (keys) or d (values)
    const int qg = tid >> 6;      // 0..3

    for (int i = tid; i < UU * 64; i += 256)
        sq[i >> 6][i & 63] = g_selq[(size_t)bh * UU * 64 + i] * 0.125f;  // hd^-0.5
    if (tid < UU) { sm[tid] = -INFINITY; sl[tid] = 0.f; }

    float acc[12];
#pragma unroll
    for (int qi = 0; qi < 12; qi++) acc[qi] = 0.f;

    const float* kbase = g_k + ((size_t)bh * SS + sp * CHUNK) * HD;
    const float* vbase = g_v + ((size_t)bh * SS + sp * CHUNK) * HD;
    __syncthreads();

    for (int t = 0; t < CHUNK / 64; t++) {
        const float* kp = kbase + t * 64 * HD;
#pragma unroll
        for (int p = 0; p < 4; p++) {
            int id = tid + p * 256;
            int r = id >> 4;
            int c = (id & 15) * 4;
            float4 v = *(const float4*)(kp + r * HD + c);
            KV[r][c + 0] = v.x; KV[r][c + 1] = v.y;
            KV[r][c + 2] = v.z; KV[r][c + 3] = v.w;
        }
        __syncthreads();

        float dots[12];
#pragma unroll
        for (int qi = 0; qi < 12; qi++) dots[qi] = 0.f;
#pragma unroll
        for (int d4 = 0; d4 < 64; d4 += 4) {
            float k0 = KV[lane][d4 + 0];
            float k1 = KV[lane][d4 + 1];
            float k2 = KV[lane][d4 + 2];
            float k3 = KV[lane][d4 + 3];
#pragma unroll
            for (int qi = 0; qi < 12; qi++) {
                int q = qg + qi * 4;
                if (q < UU) {
                    float4 qv = *(const float4*)(&sq[q][d4]);
                    dots[qi] += qv.x * k0 + qv.y * k1 + qv.z * k2 + qv.w * k3;
                }
            }
        }
#pragma unroll
        for (int qi = 0; qi < 12; qi++) {
            int q = qg + qi * 4;
            if (q < UU) P[q][lane] = dots[qi];
        }
        __syncthreads();

        if (tid < UU) {
            float mloc = -INFINITY;
#pragma unroll
            for (int j = 0; j < 64; j++) mloc = fmaxf(mloc, P[tid][j]);
            float mnew = fmaxf(sm[tid], mloc);
            salpha[tid] = __expf(sm[tid] - mnew);
            sm[tid] = mnew;
        }
        const float* vp = vbase + t * 64 * HD;
#pragma unroll
        for (int p = 0; p < 4; p++) {
            int id = tid + p * 256;
            int r = id >> 4;
            int c = (id & 15) * 4;
            float4 v = *(const float4*)(vp + r * HD + c);
            KV[r][c + 0] = v.x; KV[r][c + 1] = v.y;
            KV[r][c + 2] = v.z; KV[r][c + 3] = v.w;
        }
        __syncthreads();

#pragma unroll
        for (int qi = 0; qi < 12; qi++) {
            int q = qg + qi * 4;
            if (q < UU) {
                P[q][lane] = __expf(P[q][lane] - sm[q]);
                acc[qi] *= salpha[q];
            }
        }
        __syncthreads();

        if (tid < UU) {
            float lsum = 0.f;
#pragma unroll
            for (int j = 0; j < 64; j++) lsum += P[tid][j];
            sl[tid] = sl[tid] * salpha[tid] + lsum;
        }
#pragma unroll
        for (int j4 = 0; j4 < 64; j4 += 4) {
            float v0 = KV[j4 + 0][lane];
            float v1 = KV[j4 + 1][lane];
            float v2 = KV[j4 + 2][lane];
            float v3 = KV[j4 + 3][lane];
#pragma unroll
            for (int qi = 0; qi < 12; qi++) {
                int q = qg + qi * 4;
                if (q < UU) {
                    float4 pv = *(const float4*)(&P[q][j4]);
                    acc[qi] += pv.x * v0 + pv.y * v1 + pv.z * v2 + pv.w * v3;
                }
            }
        }
        __syncthreads();
    }

    const int pbase = (bh * NSPLIT + sp) * UU;
    if (tid < UU) { g_pm[pbase + tid] = sm[tid]; g_pl[pbase + tid] = sl[tid]; }
#pragma unroll
    for (int qi = 0; qi < 12; qi++) {
        int q = qg + qi * 4;
        if (q < UU) g_pacc[((size_t)(pbase + q)) * HD + lane] = acc[qi];
    }
}

// ------------------------- split-K merge -------------------------
__global__ __launch_bounds__(64) void merge_kernel()
{
    const int bh = blockIdx.x, u = blockIdx.y;
    const int d = threadIdx.x;
    float M = -INFINITY;
#pragma unroll
    for (int i = 0; i < NSPLIT; i++)
        M = fmaxf(M, g_pm[(bh * NSPLIT + i) * UU + u]);
    float L = 0.f, ctx = 0.f;
    for (int i = 0; i < NSPLIT; i++) {
        int pi = (bh * NSPLIT + i) * UU + u;
        float w = __expf(g_pm[pi] - M);
        L += g_pl[pi] * w;
        ctx += g_pacc[(size_t)pi * HD + d] * w;
    }
    g_selctx[(bh * UU + u) * HD + d] = ctx / L;
}

// ------------------------- output base, broadcast, corrections -------------------------
__global__ __launch_bounds__(512)
void base_kernel(const float* __restrict__ Wo, const float* __restrict__ bo)
{
    __shared__ float vm[DD];
    const int b = blockIdx.x;
    const int n = threadIdx.x;
    vm[n] = g_vsum[b * DD + n] * (1.f / SS);
    __syncthreads();
    float a = bo[n];
    for (int kk = 0; kk < DD; kk++)
        a = fmaf(vm[kk], Wo[(size_t)kk * DD + n], a);
    g_base[b * DD + n] = a;
}

__global__ __launch_bounds__(256) void bcast_kernel(float* __restrict__ out)
{
    __shared__ float4 bs[128];
    const int row0 = blockIdx.x * 16;
    const int b = row0 >> 13;
    if (threadIdx.x < 128)
        bs[threadIdx.x] = ((const float4*)(g_base + b * DD))[threadIdx.x];
    __syncthreads();
    float4* o = (float4*)out + (size_t)row0 * 128;
    for (int i = threadIdx.x; i < 16 * 128; i += 256)
        o[i] = bs[i & 127];
}

__global__ __launch_bounds__(512)
void corr_kernel(const float* __restrict__ Wo, float* __restrict__ out)
{
    __shared__ float delta[64];
    __shared__ int ssel;
    const int bh = blockIdx.x, u = blockIdx.y;
    const int b = bh >> 3, h = bh & 7;
    const int tid = threadIdx.x;
    if (tid == 0) ssel = g_top[bh * UU + u];
    if (tid < 64)
        delta[tid] = g_selctx[(bh * UU + u) * HD + tid]
                   - g_vsum[bh * HD + tid] * (1.f / SS);
    __syncthreads();
    const int s = ssel;
    float a = 0.f;
#pragma unroll
    for (int d = 0; d < 64; d++)
        a = fmaf(delta[d], Wo[(size_t)(h * HD + d) * DD + tid], a);
    atomicAdd(out + ((size_t)b * SS + s) * DD + tid, a);
}

// ------------------------- launch -------------------------
extern "C" void kernel_launch(void* const* d_in, const int* in_sizes, int n_in,
                              void* d_out, int out_size)
{
    (void)in_sizes; (void)n_in; (void)out_size;
    const float* x  = (const float*)d_in[0];
    const float* Wq = (const float*)d_in[1];
    const float* bq = (const float*)d_in[2];
    const float* Wk = (const float*)d_in[3];
    const float* bk = (const float*)d_in[4];
    const float* Wv = (const float*)d_in[5];
    const float* bv = (const float*)d_in[6];
    const float* Wo = (const float*)d_in[7];
    const float* bo = (const float*)d_in[8];
    float* out = (float*)d_out;

    dim3 pg(BB * SS / 128, DD / 128);
    zero_sp<<<BH * SS / 256, 256>>>();
    proj_tc<0><<<pg, 256>>>(x, Wq, bq);       // sparsity (tf32 approx, candidates)
    proj_tc<1><<<pg, 256>>>(x, Wk, bk);       // k head-major
    proj_tc<2><<<pg, 256>>>(x, Wv, bv);       // v head-major
    topk_kernel<<<BH, 256>>>();               // approx top-64 candidates
    cand_refine<<<dim3(BH, NC), 64>>>(x, Wq, bq);  // exact fp32 q rows + sparsity
    final_sel<<<BH, 64>>>();                  // exact top-45 + selq
    vsum_kernel<<<dim3(BH, 32), 256>>>();
    attn_kernel<<<dim3(BH, NSPLIT), 256>>>();
    merge_kernel<<<dim3(BH, UU), HD>>>();
    base_kernel<<<BB, DD>>>(Wo, bo);
    bcast_kernel<<<BB * SS / 16, 256>>>(out);
    corr_kernel<<<dim3(BH, UU), DD>>>(Wo, out);
}

// round 4
// speedup vs baseline: 2.3709x; 2.3264x over previous
#include <cuda_runtime.h>
#include <math.h>
#include <stdint.h>

// Problem constants (fixed by setup_inputs)
#define BB 4
#define SS 8192
#define DD 512
#define HH 8
#define HD 64
#define BH 32      // B*H
#define UU 45      // int(5*ln(8193)) = 45 selected queries per (b,h)
#define NC 64      // candidate count for exact refinement
#define TPART 8    // top-k partitions per (b,h)
#define NSPLIT 16
#define CHUNK 512  // SS / NSPLIT

// ------------------------- device scratch -------------------------
static __device__ __align__(16) float g_k[(size_t)BH*SS*HD];      // 64 MB [bh][s][d]
static __device__ __align__(16) float g_v[(size_t)BH*SS*HD];      // 64 MB [bh][s][d]
static __device__ float g_sp[BH*SS];                               // approx ||q||^2 (bf16 gemm)
static __device__ float g_pcv[BH*TPART*NC];
static __device__ int   g_pci[BH*TPART*NC];
static __device__ int   g_cand[BH*NC];
static __device__ float g_csp[BH*NC];                              // exact ||q||^2 of candidates
static __device__ __align__(16) float g_cq[BH*NC*HD];              // exact q rows of candidates
static __device__ int   g_top[BH*UU];
static __device__ __align__(16) float g_selq[BH*UU*HD];
static __device__ float g_selctx[BH*UU*HD];
static __device__ float g_vsum[BB*DD];                             // sum over S of v (no bias)
static __device__ __align__(16) float g_base[BB*DD];
static __device__ float g_pm[BH*NSPLIT*UU];
static __device__ float g_pl[BH*NSPLIT*UU];
static __device__ __align__(16) float g_pacc[(size_t)BH*NSPLIT*UU*HD];

// pack two floats to bf16x2 (lo -> bits[15:0], hi -> bits[31:16])
__device__ __forceinline__ uint32_t pk(float lo, float hi) {
    uint32_t r;
    asm("cvt.rn.bf16x2.f32 %0, %1, %2;" : "=r"(r) : "f"(hi), "f"(lo));
    return r;
}

__device__ __forceinline__ void ldsm4(uint32_t& r0, uint32_t& r1, uint32_t& r2,
                                      uint32_t& r3, uint32_t addr) {
    asm volatile("ldmatrix.sync.aligned.m8n8.x4.shared.b16 {%0,%1,%2,%3}, [%4];"
                 : "=r"(r0), "=r"(r1), "=r"(r2), "=r"(r3) : "r"(addr));
}
__device__ __forceinline__ void ldsm4t(uint32_t& r0, uint32_t& r1, uint32_t& r2,
                                       uint32_t& r3, uint32_t addr) {
    asm volatile("ldmatrix.sync.aligned.m8n8.x4.trans.shared.b16 {%0,%1,%2,%3}, [%4];"
                 : "=r"(r0), "=r"(r1), "=r"(r2), "=r"(r3) : "r"(addr));
}
__device__ __forceinline__ void mma16816(float* c, const uint32_t* a,
                                         uint32_t b0, uint32_t b1) {
    asm volatile(
        "mma.sync.aligned.m16n8k16.row.col.f32.bf16.bf16.f32 "
        "{%0,%1,%2,%3}, {%4,%5,%6,%7}, {%8,%9}, {%0,%1,%2,%3};\n"
        : "+f"(c[0]), "+f"(c[1]), "+f"(c[2]), "+f"(c[3])
        : "r"(a[0]), "r"(a[1]), "r"(a[2]), "r"(a[3]), "r"(b0), "r"(b1));
}

// ------------------------- zero kernel -------------------------
__global__ void zero_sp()
{
    int i = blockIdx.x * 256 + threadIdx.x;
    g_sp[i] = 0.f;                      // grid sized exactly BH*SS/256
    if (i < BB * DD) g_vsum[i] = 0.f;
}

// ------------------------- bf16 tensor-core projection GEMM -------------------------
// C = X @ W + bias. Tile 128x128, BK=32, double-buffered smem, 8 warps (2M x 4N),
// warp tile 64x32, mma.m16n8k16.bf16, ldmatrix with XOR-16B swizzle.
// MODE 0: q path -> per-head row sum-of-squares into g_sp (atomicAdd)
// MODE 1: write head-major k   MODE 2: write head-major v + fused column sums (g_vsum)
template<int MODE>
__global__ __launch_bounds__(256)
void proj_bf(const float* __restrict__ X, const float* __restrict__ W,
             const float* __restrict__ bias)
{
    // A: [128 rows][32 bf16] per buffer; row = 64B = 4x16B units, swizzle u^((r>>1)&3)
    // B: [32 rows][128 bf16] per buffer; row = 256B = 16x16B units, swizzle u^(r&7)
    __shared__ __align__(16) uint32_t sAm[2][2048];   // 8 KB each
    __shared__ __align__(16) uint32_t sBm[2][2048];   // 8 KB each

    const int tid = threadIdx.x;
    const int lane = tid & 31, wid = tid >> 5;
    const int mwarp = wid >> 2, nwarp = wid & 3;
    const int m0 = blockIdx.x * 128, n0 = blockIdx.y * 128;

    // loader roles
    const int rowA = tid >> 1, halfA = tid & 1;   // A: 128 rows x 2 halves (16 floats each)
    const int rowB = tid >> 3, segB = tid & 7;    // B: 32 rows x 8 segs (16 floats each)
    const float* gA = X + (size_t)(m0 + rowA) * DD + halfA * 16;
    const float* gB = W + (size_t)rowB * DD + n0 + segB * 16;

    float4 a4[4], b4[4];
#pragma unroll
    for (int i = 0; i < 4; i++) a4[i] = *(const float4*)(gA + i * 4);
#pragma unroll
    for (int i = 0; i < 4; i++) b4[i] = *(const float4*)(gB + i * 4);

    float acc[4][4][4];
#pragma unroll
    for (int mi = 0; mi < 4; mi++)
#pragma unroll
        for (int ni = 0; ni < 4; ni++)
#pragma unroll
            for (int c = 0; c < 4; c++) acc[mi][ni][c] = 0.f;

    const uint32_t aBase = (uint32_t)__cvta_generic_to_shared(&sAm[0][0]);
    const uint32_t bBase = (uint32_t)__cvta_generic_to_shared(&sBm[0][0]);

    // ldmatrix lane geometry
    const int ro  = lane & 15;          // row offset within 16-row block
    const int ch2 = (lane >> 4) & 1;    // k-half / n-half select
    const int rs2 = (ro >> 1) & 3;      // A swizzle term
    const int rs7 = ro & 7;             // B swizzle term

    auto stage = [&](int buf) {
#pragma unroll
        for (int i = 0; i < 2; i++) {
            uint32_t w0 = pk(a4[2*i].x, a4[2*i].y);
            uint32_t w1 = pk(a4[2*i].z, a4[2*i].w);
            uint32_t w2 = pk(a4[2*i+1].x, a4[2*i+1].y);
            uint32_t w3 = pk(a4[2*i+1].z, a4[2*i+1].w);
            int u = (halfA * 2 + i) ^ ((rowA >> 1) & 3);
            *(uint4*)&sAm[buf][rowA * 16 + u * 4] = make_uint4(w0, w1, w2, w3);
        }
#pragma unroll
        for (int i = 0; i < 2; i++) {
            uint32_t w0 = pk(b4[2*i].x, b4[2*i].y);
            uint32_t w1 = pk(b4[2*i].z, b4[2*i].w);
            uint32_t w2 = pk(b4[2*i+1].x, b4[2*i+1].y);
            uint32_t w3 = pk(b4[2*i+1].z, b4[2*i+1].w);
            int u = (segB * 2 + i) ^ (rowB & 7);
            *(uint4*)&sBm[buf][rowB * 64 + u * 4] = make_uint4(w0, w1, w2, w3);
        }
    };

    stage(0);
    __syncthreads();

    for (int chn = 0; chn < 16; chn++) {
        if (chn < 15) {
            const float* pA = gA + (chn + 1) * 32;
            const float* pB = gB + (size_t)(chn + 1) * 32 * DD;
#pragma unroll
            for (int i = 0; i < 4; i++) a4[i] = *(const float4*)(pA + i * 4);
#pragma unroll
            for (int i = 0; i < 4; i++) b4[i] = *(const float4*)(pB + i * 4);
        }
        // compute on buffer chn&1
        {
            const uint32_t ab = aBase + (chn & 1) * 8192;
            const uint32_t bb = bBase + (chn & 1) * 8192;
#pragma unroll
            for (int kblk = 0; kblk < 2; kblk++) {
                uint32_t af[4][4];
#pragma unroll
                for (int mi = 0; mi < 4; mi++) {
                    int row = mwarp * 64 + mi * 16 + ro;
                    int u = (kblk * 2 + ch2) ^ rs2;
                    ldsm4(af[mi][0], af[mi][1], af[mi][2], af[mi][3],
                          ab + (row * 16 + u * 4) * 4);
                }
                uint32_t bf[2][4];
#pragma unroll
                for (int np = 0; np < 2; np++) {
                    int row = kblk * 16 + ro;
                    int u = (nwarp * 4 + np * 2 + ch2) ^ rs7;
                    ldsm4t(bf[np][0], bf[np][1], bf[np][2], bf[np][3],
                           bb + (row * 64 + u * 4) * 4);
                }
#pragma unroll
                for (int mi = 0; mi < 4; mi++)
#pragma unroll
                    for (int ni = 0; ni < 4; ni++)
                        mma16816(acc[mi][ni], af[mi],
                                 bf[ni >> 1][(ni & 1) * 2], bf[ni >> 1][(ni & 1) * 2 + 1]);
            }
        }
        if (chn < 15) stage((chn + 1) & 1);
        __syncthreads();
    }

    // ---------------- epilogue ----------------
    // C frag: c0=C[g][t2], c1=C[g][t2+1], c2=C[g+8][t2], c3=C[g+8][t2+1]
    const int g = lane >> 2, tig = lane & 3;

    float bn[4][2];
#pragma unroll
    for (int ni = 0; ni < 4; ni++) {
        int n = n0 + nwarp * 32 + ni * 8 + tig * 2;
        bn[ni][0] = bias[n];
        bn[ni][1] = bias[n + 1];
    }

    if (MODE == 0) {
        const int h = (n0 + nwarp * 32) >> 6;   // warp's 32 cols lie in one head
#pragma unroll
        for (int mi = 0; mi < 4; mi++) {
            int m = m0 + mwarp * 64 + mi * 16 + g;
            int b = m >> 13;
            int s = m & (SS - 1);
            float ss0 = 0.f, ss1 = 0.f;
#pragma unroll
            for (int ni = 0; ni < 4; ni++) {
                float c0 = acc[mi][ni][0] + bn[ni][0];
                float c1 = acc[mi][ni][1] + bn[ni][1];
                float c2 = acc[mi][ni][2] + bn[ni][0];
                float c3 = acc[mi][ni][3] + bn[ni][1];
                ss0 = fmaf(c0, c0, fmaf(c1, c1, ss0));
                ss1 = fmaf(c2, c2, fmaf(c3, c3, ss1));
            }
            ss0 += __shfl_xor_sync(0xffffffffu, ss0, 1);
            ss0 += __shfl_xor_sync(0xffffffffu, ss0, 2);
            ss1 += __shfl_xor_sync(0xffffffffu, ss1, 1);
            ss1 += __shfl_xor_sync(0xffffffffu, ss1, 2);
            if (tig == 0) {
                atomicAdd(&g_sp[(b * HH + h) * SS + s], ss0);
                atomicAdd(&g_sp[(b * HH + h) * SS + s + 8], ss1);
            }
        }
    } else {
        float* __restrict__ dst = (MODE == 1) ? g_k : g_v;
#pragma unroll
        for (int mi = 0; mi < 4; mi++) {
            int m = m0 + mwarp * 64 + mi * 16 + g;
            int b = m >> 13;
            int s = m & (SS - 1);
#pragma unroll
            for (int ni = 0; ni < 4; ni++) {
                int n = n0 + nwarp * 32 + ni * 8 + tig * 2;
                int h = n >> 6, d = n & 63;
                float2 lo = {acc[mi][ni][0] + bn[ni][0], acc[mi][ni][1] + bn[ni][1]};
                float2 hi = {acc[mi][ni][2] + bn[ni][0], acc[mi][ni][3] + bn[ni][1]};
                *(float2*)(dst + (((size_t)(b * HH + h)) * SS + s) * HD + d)     = lo;
                *(float2*)(dst + (((size_t)(b * HH + h)) * SS + s + 8) * HD + d) = hi;
            }
        }
        if (MODE == 2) {
            // fused column sums over this warp's 64 rows (bias excluded; added later)
            const int b = m0 >> 13;
#pragma unroll
            for (int ni = 0; ni < 4; ni++) {
                float s0 = 0.f, s1 = 0.f;
#pragma unroll
                for (int mi = 0; mi < 4; mi++) {
                    s0 += acc[mi][ni][0] + acc[mi][ni][2];
                    s1 += acc[mi][ni][1] + acc[mi][ni][3];
                }
#pragma unroll
                for (int off = 4; off <= 16; off <<= 1) {
                    s0 += __shfl_xor_sync(0xffffffffu, s0, off);
                    s1 += __shfl_xor_sync(0xffffffffu, s1, off);
                }
                if (g == 0) {
                    int n = n0 + nwarp * 32 + ni * 8 + tig * 2;
                    atomicAdd(&g_vsum[b * DD + n], s0);
                    atomicAdd(&g_vsum[b * DD + n + 1], s1);
                }
            }
        }
    }
}

// ------------------------- partitioned top-64 candidates -------------------------
__global__ __launch_bounds__(256) void topk_part()
{
    __shared__ float sv[1024];
    __shared__ float wv[8];
    __shared__ int   wi[8];
    const int bh = blockIdx.x, part = blockIdx.y;
    const int tid = threadIdx.x, lane = tid & 31, wid = tid >> 5;
    const int base = bh * SS + part * 1024;
#pragma unroll
    for (int i = 0; i < 4; i++) sv[tid + i * 256] = g_sp[base + tid + i * 256];
    __syncthreads();
    for (int it = 0; it < NC; it++) {
        float best = -INFINITY; int bi = 0;
#pragma unroll
        for (int i = 0; i < 4; i++) {
            int j = tid + i * 256;
            float v = sv[j];
            if (v > best) { best = v; bi = j; }     // keeps lowest index on ties
        }
#pragma unroll
        for (int off = 16; off > 0; off >>= 1) {
            float ov = __shfl_down_sync(0xffffffffu, best, off);
            int   oi = __shfl_down_sync(0xffffffffu, bi, off);
            if (ov > best || (ov == best && oi < bi)) { best = ov; bi = oi; }
        }
        if (lane == 0) { wv[wid] = best; wi[wid] = bi; }
        __syncthreads();
        if (tid == 0) {
            float bb = wv[0]; int x = wi[0];
#pragma unroll
            for (int w = 1; w < 8; w++)
                if (wv[w] > bb || (wv[w] == bb && wi[w] < x)) { bb = wv[w]; x = wi[w]; }
            g_pcv[(bh * TPART + part) * NC + it] = bb;
            g_pci[(bh * TPART + part) * NC + it] = part * 1024 + x;
            sv[x] = -INFINITY;
        }
        __syncthreads();
    }
}

__global__ __launch_bounds__(512) void topk_merge()
{
    __shared__ float vv[512];
    __shared__ int   ii[512];
    const int bh = blockIdx.x;
    const int t = threadIdx.x;
    vv[t] = g_pcv[bh * 512 + t];
    ii[t] = g_pci[bh * 512 + t];
    __syncthreads();
    float myv = vv[t]; int myi = ii[t];
    int rank = 0;
    for (int j = 0; j < 512; j++) {
        float o = vv[j];
        rank += (o > myv) || (o == myv && ii[j] < myi);
    }
    if (rank < NC) g_cand[bh * NC + rank] = myi;
}

// ------------------------- exact fp32 recompute of candidate q rows -------------------------
// grid (BH, NC/8), 256 threads: 8 warps, warp u handles candidate grp*8+u.
__global__ __launch_bounds__(256)
void cand_refine(const float* __restrict__ X, const float* __restrict__ Wq,
                 const float* __restrict__ bq)
{
    __shared__ float sW[64][65];
    __shared__ float sX[8][64];
    __shared__ int   sS[8];
    const int bh = blockIdx.x, grp = blockIdx.y;
    const int b = bh >> 3, h = bh & 7;
    const int tid = threadIdx.x;
    const int u = tid >> 5, lane = tid & 31;
    if (tid < 8) sS[tid] = g_cand[bh * NC + grp * 8 + tid];
    float acc0 = 0.f, acc1 = 0.f;
    __syncthreads();
    for (int kc = 0; kc < 8; kc++) {
#pragma unroll
        for (int i = 0; i < 16; i++) {
            int idx = tid + i * 256;
            sW[idx >> 6][idx & 63] = Wq[(size_t)(kc * 64 + (idx >> 6)) * DD + h * HD + (idx & 63)];
        }
#pragma unroll
        for (int i = 0; i < 2; i++) {
            int idx = tid + i * 256;
            sX[idx >> 6][idx & 63] = X[((size_t)b * SS + sS[idx >> 6]) * DD + kc * 64 + (idx & 63)];
        }
        __syncthreads();
#pragma unroll
        for (int k = 0; k < 64; k++) {
            float xv = sX[u][k];
            acc0 = fmaf(xv, sW[k][lane], acc0);
            acc1 = fmaf(xv, sW[k][lane + 32], acc1);
        }
        __syncthreads();
    }
    acc0 += bq[h * HD + lane];
    acc1 += bq[h * HD + lane + 32];
    const int cu = bh * NC + grp * 8 + u;
    g_cq[cu * HD + lane] = acc0;
    g_cq[cu * HD + lane + 32] = acc1;
    float ss = acc0 * acc0 + acc1 * acc1;
#pragma unroll
    for (int off = 16; off > 0; off >>= 1) ss += __shfl_xor_sync(0xffffffffu, ss, off);
    if (lane == 0) g_csp[cu] = ss;
}

// ------------------------- exact top-45 among candidates -------------------------
__global__ __launch_bounds__(64) void final_sel()
{
    __shared__ float vv[NC];
    __shared__ int   ssd[NC];
    __shared__ int   slot[UU];
    const int bh = blockIdx.x;
    const int tid = threadIdx.x;
    float myv = g_csp[bh * NC + tid];
    int   mys = g_cand[bh * NC + tid];
    vv[tid] = myv; ssd[tid] = mys;
    __syncthreads();
    int rank = 0;
#pragma unroll
    for (int j = 0; j < NC; j++) {
        float o = vv[j];
        if (o > myv || (o == myv && ssd[j] < mys)) rank++;
    }
    if (rank < UU) { g_top[bh * UU + rank] = mys; slot[rank] = tid; }
    __syncthreads();
    for (int u = 0; u < UU; u++) {
        int c = slot[u];
        g_selq[(bh * UU + u) * HD + tid] = g_cq[(bh * NC + c) * HD + tid];
    }
}

// ------------------------- attention (flash split-K over S) -------------------------
__global__ __launch_bounds__(256)
void attn_kernel()
{
    __shared__ __align__(16) float sq[UU][64];    // pre-scaled queries
    __shared__ float KV[64][65];                  // K then V tile (reused)
    __shared__ __align__(16) float P[UU][68];     // scores / probabilities
    __shared__ float sm[UU], sl[UU], salpha[UU];

    const int bh = blockIdx.x;
    const int sp = blockIdx.y;
    const int tid = threadIdx.x;
    const int lane = tid & 63;    // j (keys) or d (values)
    const int qg = tid >> 6;      // 0..3

    for (int i = tid; i < UU * 64; i += 256)
        sq[i >> 6][i & 63] = g_selq[(size_t)bh * UU * 64 + i] * 0.125f;  // hd^-0.5
    if (tid < UU) { sm[tid] = -INFINITY; sl[tid] = 0.f; }

    float acc[12];
#pragma unroll
    for (int qi = 0; qi < 12; qi++) acc[qi] = 0.f;

    const float* kbase = g_k + ((size_t)bh * SS + sp * CHUNK) * HD;
    const float* vbase = g_v + ((size_t)bh * SS + sp * CHUNK) * HD;
    __syncthreads();

    for (int t = 0; t < CHUNK / 64; t++) {
        const float* kp = kbase + t * 64 * HD;
#pragma unroll
        for (int p = 0; p < 4; p++) {
            int id = tid + p * 256;
            int r = id >> 4;
            int c = (id & 15) * 4;
            float4 v = *(const float4*)(kp + r * HD + c);
            KV[r][c + 0] = v.x; KV[r][c + 1] = v.y;
            KV[r][c + 2] = v.z; KV[r][c + 3] = v.w;
        }
        __syncthreads();

        float dots[12];
#pragma unroll
        for (int qi = 0; qi < 12; qi++) dots[qi] = 0.f;
#pragma unroll
        for (int d4 = 0; d4 < 64; d4 += 4) {
            float k0 = KV[lane][d4 + 0];
            float k1 = KV[lane][d4 + 1];
            float k2 = KV[lane][d4 + 2];
            float k3 = KV[lane][d4 + 3];
#pragma unroll
            for (int qi = 0; qi < 12; qi++) {
                int q = qg + qi * 4;
                if (q < UU) {
                    float4 qv = *(const float4*)(&sq[q][d4]);
                    dots[qi] += qv.x * k0 + qv.y * k1 + qv.z * k2 + qv.w * k3;
                }
            }
        }
#pragma unroll
        for (int qi = 0; qi < 12; qi++) {
            int q = qg + qi * 4;
            if (q < UU) P[q][lane] = dots[qi];
        }
        __syncthreads();

        if (tid < UU) {
            float mloc = -INFINITY;
#pragma unroll
            for (int j = 0; j < 64; j++) mloc = fmaxf(mloc, P[tid][j]);
            float mnew = fmaxf(sm[tid], mloc);
            salpha[tid] = __expf(sm[tid] - mnew);
            sm[tid] = mnew;
        }
        const float* vp = vbase + t * 64 * HD;
#pragma unroll
        for (int p = 0; p < 4; p++) {
            int id = tid + p * 256;
            int r = id >> 4;
            int c = (id & 15) * 4;
            float4 v = *(const float4*)(vp + r * HD + c);
            KV[r][c + 0] = v.x; KV[r][c + 1] = v.y;
            KV[r][c + 2] = v.z; KV[r][c + 3] = v.w;
        }
        __syncthreads();

#pragma unroll
        for (int qi = 0; qi < 12; qi++) {
            int q = qg + qi * 4;
            if (q < UU) {
                P[q][lane] = __expf(P[q][lane] - sm[q]);
                acc[qi] *= salpha[q];
            }
        }
        __syncthreads();

        if (tid < UU) {
            float lsum = 0.f;
#pragma unroll
            for (int j = 0; j < 64; j++) lsum += P[tid][j];
            sl[tid] = sl[tid] * salpha[tid] + lsum;
        }
#pragma unroll
        for (int j4 = 0; j4 < 64; j4 += 4) {
            float v0 = KV[j4 + 0][lane];
            float v1 = KV[j4 + 1][lane];
            float v2 = KV[j4 + 2][lane];
            float v3 = KV[j4 + 3][lane];
#pragma unroll
            for (int qi = 0; qi < 12; qi++) {
                int q = qg + qi * 4;
                if (q < UU) {
                    float4 pv = *(const float4*)(&P[q][j4]);
                    acc[qi] += pv.x * v0 + pv.y * v1 + pv.z * v2 + pv.w * v3;
                }
            }
        }
        __syncthreads();
    }

    const int pbase = (bh * NSPLIT + sp) * UU;
    if (tid < UU) { g_pm[pbase + tid] = sm[tid]; g_pl[pbase + tid] = sl[tid]; }
#pragma unroll
    for (int qi = 0; qi < 12; qi++) {
        int q = qg + qi * 4;
        if (q < UU) g_pacc[((size_t)(pbase + q)) * HD + lane] = acc[qi];
    }
}

// ------------------------- split-K merge -------------------------
__global__ __launch_bounds__(64) void merge_kernel()
{
    const int bh = blockIdx.x, u = blockIdx.y;
    const int d = threadIdx.x;
    float M = -INFINITY;
#pragma unroll
    for (int i = 0; i < NSPLIT; i++)
        M = fmaxf(M, g_pm[(bh * NSPLIT + i) * UU + u]);
    float L = 0.f, ctx = 0.f;
    for (int i = 0; i < NSPLIT; i++) {
        int pi = (bh * NSPLIT + i) * UU + u;
        float w = __expf(g_pm[pi] - M);
        L += g_pl[pi] * w;
        ctx += g_pacc[(size_t)pi * HD + d] * w;
    }
    g_selctx[(bh * UU + u) * HD + d] = ctx / L;
}

// ------------------------- output base, broadcast, corrections -------------------------
__global__ __launch_bounds__(512)
void base_kernel(const float* __restrict__ Wo, const float* __restrict__ bo,
                 const float* __restrict__ bv)
{
    __shared__ float vm[DD];
    const int b = blockIdx.x;
    const int n = threadIdx.x;
    vm[n] = g_vsum[b * DD + n] * (1.f / SS) + bv[n];
    __syncthreads();
    float a = bo[n];
    for (int kk = 0; kk < DD; kk++)
        a = fmaf(vm[kk], Wo[(size_t)kk * DD + n], a);
    g_base[b * DD + n] = a;
}

__global__ __launch_bounds__(256) void bcast_kernel(float* __restrict__ out)
{
    __shared__ float4 bs[128];
    const int row0 = blockIdx.x * 16;
    const int b = row0 >> 13;
    if (threadIdx.x < 128)
        bs[threadIdx.x] = ((const float4*)(g_base + b * DD))[threadIdx.x];
    __syncthreads();
    float4* o = (float4*)out + (size_t)row0 * 128;
    for (int i = threadIdx.x; i < 16 * 128; i += 256)
        o[i] = bs[i & 127];
}

__global__ __launch_bounds__(512)
void corr_kernel(const float* __restrict__ Wo, const float* __restrict__ bv,
                 float* __restrict__ out)
{
    __shared__ float delta[64];
    __shared__ int ssel;
    const int bh = blockIdx.x, u = blockIdx.y;
    const int b = bh >> 3, h = bh & 7;
    const int tid = threadIdx.x;
    if (tid == 0) ssel = g_top[bh * UU + u];
    if (tid < 64)
        delta[tid] = g_selctx[(bh * UU + u) * HD + tid]
                   - (g_vsum[bh * HD + tid] * (1.f / SS) + bv[h * HD + tid]);
    __syncthreads();
    const int s = ssel;
    float a = 0.f;
#pragma unroll
    for (int d = 0; d < 64; d++)
        a = fmaf(delta[d], Wo[(size_t)(h * HD + d) * DD + tid], a);
    atomicAdd(out + ((size_t)b * SS + s) * DD + tid, a);
}

// ------------------------- launch -------------------------
extern "C" void kernel_launch(void* const* d_in, const int* in_sizes, int n_in,
                              void* d_out, int out_size)
{
    (void)in_sizes; (void)n_in; (void)out_size;
    const float* x  = (const float*)d_in[0];
    const float* Wq = (const float*)d_in[1];
    const float* bq = (const float*)d_in[2];
    const float* Wk = (const float*)d_in[3];
    const float* bk = (const float*)d_in[4];
    const float* Wv = (const float*)d_in[5];
    const float* bv = (const float*)d_in[6];
    const float* Wo = (const float*)d_in[7];
    const float* bo = (const float*)d_in[8];
    float* out = (float*)d_out;

    dim3 pg(BB * SS / 128, DD / 128);
    zero_sp<<<BH * SS / 256, 256>>>();
    proj_bf<0><<<pg, 256>>>(x, Wq, bq);       // sparsity (bf16 approx, candidates)
    proj_bf<1><<<pg, 256>>>(x, Wk, bk);       // k head-major
    proj_bf<2><<<pg, 256>>>(x, Wv, bv);       // v head-major + fused vsum
    topk_part<<<dim3(BH, TPART), 256>>>();
    topk_merge<<<BH, 512>>>();
    cand_refine<<<dim3(BH, NC / 8), 256>>>(x, Wq, bq);
    final_sel<<<BH, 64>>>();
    attn_kernel<<<dim3(BH, NSPLIT), 256>>>();
    merge_kernel<<<dim3(BH, UU), HD>>>();
    base_kernel<<<BB, DD>>>(Wo, bo, bv);
    bcast_kernel<<<BB * SS / 16, 256>>>(out);
    corr_kernel<<<dim3(BH, UU), DD>>>(Wo, bv, out);
}